// round 3
// baseline (speedup 1.0000x reference)
#include <cuda_runtime.h>
#include <math.h>

#define BB 64
#define PP 2048
#define LL 512
#define DM 512
#define HH 8
#define DK 64
#define LN_EPS 1e-5f

// ---------------- scratch (device globals; no allocation) ----------------
__device__ float g_wg[BB * HH * LL];      // g_l-folded, 1/8-scaled W_k^T Q   [b][h][l]
__device__ float g_Wsum[BB * HH];
__device__ float g_wb[BB * HH];
__device__ float g_resid[BB * DM];
__device__ float g_scores[(size_t)BB * PP * HH];   // [b][p][h]
__device__ float g_mean[BB * PP];
__device__ float g_rstd[BB * PP];
__device__ float g_coeff[(size_t)BB * PP * HH];    // attn * rstd, [b][p][h]
__device__ float g_acc2[BB * HH];                  // sum_p attn*r*m
__device__ float g_spart[(size_t)BB * 8 * HH * LL];// [b][chunk][h][l]

// ---------------- K1: per-batch setup --------------------------------------
__global__ void k1_setup(const float* __restrict__ xt,
                         const float* __restrict__ Wq,
                         const float* __restrict__ Wk,
                         const float* __restrict__ lnqg, const float* __restrict__ lnqb,
                         const float* __restrict__ lnkvg, const float* __restrict__ lnkvb,
                         const float* __restrict__ resW, const float* __restrict__ resb) {
    int b = blockIdx.x, t = threadIdx.x;
    __shared__ float sx[LL];     // raw x_trafic row
    __shared__ float sq[LL];     // LN(query)
    __shared__ float sQ[DM];     // Q row
    __shared__ float sw[HH * LL];// raw folded w (pre-gamma)
    __shared__ float sred[24];

    float x0 = xt[b * LL + t];
    float x1 = xt[b * LL + t + 256];
    sx[t] = x0; sx[t + 256] = x1;

    float ps = x0 + x1;
    float pq = x0 * x0 + x1 * x1;
    #pragma unroll
    for (int o = 16; o; o >>= 1) {
        ps += __shfl_xor_sync(~0u, ps, o);
        pq += __shfl_xor_sync(~0u, pq, o);
    }
    if ((t & 31) == 0) { sred[t >> 5] = ps; sred[8 + (t >> 5)] = pq; }
    __syncthreads();
    if (t == 0) {
        float s = 0.f, q = 0.f;
        for (int i = 0; i < 8; i++) { s += sred[i]; q += sred[8 + i]; }
        float m = s * (1.0f / LL);
        float v = q * (1.0f / LL) - m * m;
        sred[16] = m;
        sred[17] = rsqrtf(v + LN_EPS);
    }
    __syncthreads();
    float mean = sred[16], rstd = sred[17];
    sq[t]       = (x0 - mean) * rstd * lnqg[t]       + lnqb[t];
    sq[t + 256] = (x1 - mean) * rstd * lnqg[t + 256] + lnqb[t + 256];
    __syncthreads();

    // Q = LN(q) @ Wq ; residual = x @ resW + resb   (thread-per-output-col)
    for (int d = t; d < DM; d += 256) {
        float qa = 0.f, ra = 0.f;
        for (int l = 0; l < LL; l++) {
            qa = fmaf(sq[l], Wq[l * DM + d], qa);
            ra = fmaf(sx[l], resW[l * DM + d], ra);
        }
        sQ[d] = qa;
        g_resid[b * DM + d] = ra + resb[d];
    }
    __syncthreads();

    // w[h][l] = (1/8) * sum_d Wk[l, h*64+d] * Q[h*64+d]
    for (int h = 0; h < HH; h++) {
        const float* Qh = sQ + h * DK;
        for (int l = t; l < LL; l += 256) {
            const float* wkrow = Wk + (size_t)l * DM + h * DK;
            float a = 0.f;
            #pragma unroll 16
            for (int d = 0; d < DK; d++) a = fmaf(wkrow[d], Qh[d], a);
            sw[h * LL + l] = a * 0.125f;   // 1/sqrt(64)
        }
    }
    __syncthreads();

    // per-head: write wg = g_l * w, reduce Wsum = sum wg, wb = sum b_l * w
    {
        int w = t >> 5, lane = t & 31;
        int h = w;   // 8 warps, one head each
        float wsum = 0.f, wbp = 0.f;
        for (int l = lane; l < LL; l += 32) {
            float wv = sw[h * LL + l];
            float wgv = wv * lnkvg[l];
            g_wg[((size_t)b * HH + h) * LL + l] = wgv;
            wsum += wgv;
            wbp  += wv * lnkvb[l];
        }
        #pragma unroll
        for (int o = 16; o; o >>= 1) {
            wsum += __shfl_xor_sync(~0u, wsum, o);
            wbp  += __shfl_xor_sync(~0u, wbp, o);
        }
        if (lane == 0) { g_Wsum[b * HH + h] = wsum; g_wb[b * HH + h] = wbp; }
    }
}

// ---------------- K2: score pass (stream x_dynamic, warp per row) ----------
__global__ void k2_scores(const float* __restrict__ xd) {
    int b = blockIdx.y, chunk = blockIdx.x;
    int t = threadIdx.x, wid = t >> 5, lane = t & 31;
    __shared__ float4 swg[HH * LL / 4];   // 16 KB
    __shared__ float sWs[HH], swb[HH];

    const float4* wgb = (const float4*)(g_wg + (size_t)b * HH * LL);
    for (int i = t; i < HH * LL / 4; i += 256) swg[i] = wgb[i];
    if (t < HH) { sWs[t] = g_Wsum[b * HH + t]; swb[t] = g_wb[b * HH + t]; }
    __syncthreads();

    int p0 = chunk * 256;
    for (int r = wid; r < 256; r += 8) {
        int p = p0 + r;
        const float4* xr = (const float4*)(xd + ((size_t)b * PP + p) * LL);
        float4 xv[4];
        #pragma unroll
        for (int j = 0; j < 4; j++) xv[j] = xr[lane + 32 * j];

        float s = 0.f, q = 0.f;
        #pragma unroll
        for (int j = 0; j < 4; j++) {
            s += xv[j].x + xv[j].y + xv[j].z + xv[j].w;
            q += xv[j].x * xv[j].x + xv[j].y * xv[j].y
               + xv[j].z * xv[j].z + xv[j].w * xv[j].w;
        }
        float dot[HH];
        #pragma unroll
        for (int h = 0; h < HH; h++) {
            float a = 0.f;
            #pragma unroll
            for (int j = 0; j < 4; j++) {
                float4 wv = swg[h * 128 + lane + 32 * j];
                a = fmaf(xv[j].x, wv.x, a);
                a = fmaf(xv[j].y, wv.y, a);
                a = fmaf(xv[j].z, wv.z, a);
                a = fmaf(xv[j].w, wv.w, a);
            }
            dot[h] = a;
        }
        #pragma unroll
        for (int o = 16; o; o >>= 1) {
            s += __shfl_xor_sync(~0u, s, o);
            q += __shfl_xor_sync(~0u, q, o);
            #pragma unroll
            for (int h = 0; h < HH; h++) dot[h] += __shfl_xor_sync(~0u, dot[h], o);
        }
        float m  = s * (1.0f / LL);
        float v  = q * (1.0f / LL) - m * m;
        float r_ = rsqrtf(v + LN_EPS);
        if (lane == 0) { g_mean[b * PP + p] = m; g_rstd[b * PP + p] = r_; }
        if (lane < HH) {
            float myd = 0.f, myWs = 0.f, mywb = 0.f;
            #pragma unroll
            for (int h = 0; h < HH; h++)
                if (lane == h) { myd = dot[h]; myWs = sWs[h]; mywb = swb[h]; }
            g_scores[((size_t)b * PP + p) * HH + lane] = r_ * (myd - m * myWs) + mywb;
        }
    }
}

// ---------------- K3: softmax + attn output + coeff + acc2 -----------------
__global__ void k3_softmax(float* __restrict__ out_attn) {
    int b = blockIdx.x, t = threadIdx.x;
    int h = t & 7;   // 256 % 8 == 0 -> each thread sticks to one head
    __shared__ float sred[256];
    __shared__ float smaxs[8], sinvs[8];
    __shared__ float satt[256 * 9];   // padded transpose buffer

    const float* sc  = g_scores + (size_t)b * PP * HH;
    const float* rst = g_rstd   + (size_t)b * PP;
    const float* mn  = g_mean   + (size_t)b * PP;

    // pass 1: max per head
    float mx = -1e30f;
    for (int i = t; i < PP * HH; i += 256) mx = fmaxf(mx, sc[i]);
    sred[t] = mx;
    __syncthreads();
    if (t < 8) {
        float m = sred[t];
        for (int k = 1; k < 32; k++) m = fmaxf(m, sred[t + 8 * k]);
        smaxs[t] = m;
    }
    __syncthreads();
    float mh = smaxs[h];

    // pass 2: sum of exp, and sum of exp*r*m (for acc2)
    float sm = 0.f, a2 = 0.f;
    for (int i = t; i < PP * HH; i += 256) {
        int p = i >> 3;
        float e = __expf(sc[i] - mh);
        sm += e;
        a2 = fmaf(e, rst[p] * mn[p], a2);
    }
    sred[t] = sm;
    __syncthreads();
    if (t < 8) {
        float s = 0.f;
        for (int k = 0; k < 32; k++) s += sred[t + 8 * k];
        sinvs[t] = 1.0f / s;
    }
    __syncthreads();
    sred[t] = a2;
    __syncthreads();
    if (t < 8) {
        float s = 0.f;
        for (int k = 0; k < 32; k++) s += sred[t + 8 * k];
        g_acc2[b * 8 + t] = s * sinvs[t];
    }
    __syncthreads();
    float inv = sinvs[h];

    // pass 3: write attn (transposed to [b][h][p]) + coeff = attn*rstd
    for (int tile = 0; tile < 8; tile++) {
        int pbase = tile * 256;
        #pragma unroll
        for (int k = 0; k < 8; k++) {
            int il = k * 256 + t;          // 0..2047 within tile
            int pl = il >> 3;              // local p
            float e = __expf(sc[(size_t)(pbase) * 8 + il] - mh) * inv;
            satt[pl * 9 + h] = e;
            g_coeff[(size_t)b * PP * 8 + (size_t)pbase * 8 + il] = e * rst[pbase + pl];
        }
        __syncthreads();
        #pragma unroll
        for (int k = 0; k < 8; k++) {
            out_attn[((size_t)b * 8 + k) * PP + pbase + t] = satt[t * 9 + k];
        }
        __syncthreads();
    }
}

// ---------------- K4: weighted-sum pass (stream x_dynamic again) -----------
__global__ void k4_wsum(const float* __restrict__ xd) {
    int b = blockIdx.y, chunk = blockIdx.x, t = threadIdx.x;
    int p0 = chunk * 256;
    const float2* xrow2 = (const float2*)(xd + ((size_t)b * PP + p0) * LL);
    const float4* cf    = (const float4*)(g_coeff + ((size_t)b * PP + p0) * 8);

    float2 acc[HH];
    #pragma unroll
    for (int hh = 0; hh < HH; hh++) acc[hh] = make_float2(0.f, 0.f);

    #pragma unroll 4
    for (int r = 0; r < 256; r++) {
        float4 c0 = __ldg(&cf[2 * r]);
        float4 c1 = __ldg(&cf[2 * r + 1]);
        float2 xv = xrow2[(size_t)r * 256 + t];   // l = 2t, 2t+1
        float cc[8] = {c0.x, c0.y, c0.z, c0.w, c1.x, c1.y, c1.z, c1.w};
        #pragma unroll
        for (int hh = 0; hh < HH; hh++) {
            acc[hh].x = fmaf(cc[hh], xv.x, acc[hh].x);
            acc[hh].y = fmaf(cc[hh], xv.y, acc[hh].y);
        }
    }
    #pragma unroll
    for (int hh = 0; hh < HH; hh++) {
        float2* sp = (float2*)(g_spart + (((size_t)(b * 8 + chunk) * HH + hh) * LL));
        sp[t] = acc[hh];
    }
}

// ---------------- K5: reduce partials, V-GEMV, residual add ----------------
__global__ void k5_out(const float* __restrict__ Wv,
                       const float* __restrict__ lnkvg,
                       const float* __restrict__ lnkvb,
                       float* __restrict__ out_ctx) {
    int b = blockIdx.x, t = threadIdx.x;
    __shared__ float ss[HH * LL];   // 16 KB

    for (int idx = t; idx < HH * LL; idx += 256) {
        float a = 0.f;
        #pragma unroll
        for (int c = 0; c < 8; c++)
            a += g_spart[((size_t)(b * 8 + c) * HH * LL) + idx];
        int hh = idx >> 9, l = idx & 511;
        ss[idx] = lnkvg[l] * (a - g_acc2[b * HH + hh]) + lnkvb[l];
    }
    __syncthreads();

    for (int d = t; d < DM; d += 256) {
        int hh = d >> 6;
        const float* sh = ss + hh * LL;
        float a = 0.f;
        for (int l = 0; l < LL; l++) a = fmaf(sh[l], Wv[(size_t)l * DM + d], a);
        out_ctx[b * DM + d] = g_resid[b * DM + d] + a;
    }
}

// ---------------- launch ---------------------------------------------------
extern "C" void kernel_launch(void* const* d_in, const int* in_sizes, int n_in,
                              void* d_out, int out_size) {
    const float* xt    = (const float*)d_in[0];   // x_trafic   (B, L)
    const float* xd    = (const float*)d_in[1];   // x_dynamic  (B, P, L)
    // d_in[2] = x_known (unused by reference)
    const float* Wq    = (const float*)d_in[3];
    const float* Wk    = (const float*)d_in[4];
    const float* Wv    = (const float*)d_in[5];
    const float* lnqg  = (const float*)d_in[6];
    const float* lnqb  = (const float*)d_in[7];
    const float* lnkvg = (const float*)d_in[8];
    const float* lnkvb = (const float*)d_in[9];
    const float* resW  = (const float*)d_in[10];
    const float* resb  = (const float*)d_in[11];

    float* out      = (float*)d_out;
    float* out_ctx  = out;                 // (B, DM)
    float* out_attn = out + BB * DM;       // (B, H, 1, P)

    k1_setup<<<BB, 256>>>(xt, Wq, Wk, lnqg, lnqb, lnkvg, lnkvb, resW, resb);
    k2_scores<<<dim3(8, BB), 256>>>(xd);
    k3_softmax<<<BB, 256>>>(out_attn);
    k4_wsum<<<dim3(8, BB), 256>>>(xd);
    k5_out<<<BB, 256>>>(Wv, lnkvg, lnkvb, out_ctx);
}